// round 1
// baseline (speedup 1.0000x reference)
#include <cuda_runtime.h>
#include <cuda_bf16.h>
#include <cstdint>

// Problem constants (fixed shapes)
#define NN    8192
#define EE    262144
#define DD    128
#define WORDS_PER_ROW (NN / 32)   // 256

// Device scratch (no allocations allowed)
__device__ uint32_t g_bits[NN * WORDS_PER_ROW];   // 8 MB binary adjacency
__device__ float    g_z[NN * DD];                 // 4 MB  z = x @ W^T + b
__device__ int      g_is64;

// ---------------------------------------------------------------------------
// 1) clear bitmask
// ---------------------------------------------------------------------------
__global__ void clear_bits_kernel() {
    int i = blockIdx.x * blockDim.x + threadIdx.x;   // 524288 threads, uint4 each
    reinterpret_cast<uint4*>(g_bits)[i] = make_uint4(0u, 0u, 0u, 0u);
}

// ---------------------------------------------------------------------------
// 2) detect int64 vs int32 edge_index encoding.
//    If int64 with values < 8192, every odd uint32 word is 0.  Checking 256
//    samples: false positive prob for int32 data ~ (1/8192)^256 ~ 0.
// ---------------------------------------------------------------------------
__global__ void detect_kernel(const uint32_t* __restrict__ edges) {
    uint32_t v = 0;
    for (int k = threadIdx.x; k < 256; k += 32) v |= edges[2 * k + 1];
    #pragma unroll
    for (int o = 16; o; o >>= 1) v |= __shfl_xor_sync(0xFFFFFFFFu, v, o);
    if (threadIdx.x == 0) g_is64 = (v == 0u) ? 1 : 0;
}

// ---------------------------------------------------------------------------
// 3) scatter edges into bitmask.  adj[src, dst] = 1  (set semantics).
//    Layout of edge_index buffer: [0..E) = src row, [E..2E) = dst row.
// ---------------------------------------------------------------------------
__global__ void scatter_kernel(const void* __restrict__ edges) {
    int e = blockIdx.x * blockDim.x + threadIdx.x;
    if (e >= EE) return;
    int s, d;
    if (g_is64) {
        const long long* p = (const long long*)edges;
        s = (int)p[e];
        d = (int)p[EE + e];
    } else {
        const int* p = (const int*)edges;
        s = p[e];
        d = p[EE + e];
    }
    atomicOr(&g_bits[s * WORDS_PER_ROW + (d >> 5)], 1u << (d & 31));
}

// ---------------------------------------------------------------------------
// 4) z = x @ W^T + b    (M=8192, N=128, K=128, fp32)
//    Block: 32 rows, 128 threads (thread t -> output col o = t).
//    K tiled by 32.  W tile stored in shared in a [kl/4][o][kl%3] float4-
//    friendly layout so the inner loop is pure float4 LDS + FFMA, with
//    conflict-free reads (lane o start bank = 4*o mod 32, phases disjoint).
// ---------------------------------------------------------------------------
#define GEMM_ROWS 32
__global__ void __launch_bounds__(128) gemm_kernel(
    const float* __restrict__ x, const float* __restrict__ W,
    const float* __restrict__ b, float* __restrict__ z)
{
    __shared__ float Wtv[32 * 128];         // 16 KB, one K-tile of W
    __shared__ float xs[GEMM_ROWS * 32];    // 4 KB,  one K-tile of x rows

    const int t    = threadIdx.x;           // 0..127
    const int o    = t;                     // output column
    const int row0 = blockIdx.x * GEMM_ROWS;

    float acc[GEMM_ROWS];
    const float bias = b[o];
    #pragma unroll
    for (int r = 0; r < GEMM_ROWS; r++) acc[r] = bias;

    for (int kt = 0; kt < DD; kt += 32) {
        __syncthreads();   // protect previous tile reads before overwrite
        // load W tile: 128 o x 32 k -> 4096 elems, 32 per thread, coalesced
        #pragma unroll 8
        for (int j = 0; j < 32; j++) {
            int i  = t + j * 128;
            int ow = i >> 5;
            int kl = i & 31;
            Wtv[(kl >> 2) * 512 + ow * 4 + (kl & 3)] = W[ow * DD + kt + kl];
        }
        // load x tile: 32 rows x 32 k -> 1024 elems, 8 per thread, coalesced
        #pragma unroll
        for (int j = 0; j < 8; j++) {
            int i  = t + j * 128;
            int r  = i >> 5;
            int kl = i & 31;
            xs[r * 32 + kl] = x[(row0 + r) * DD + kt + kl];
        }
        __syncthreads();

        #pragma unroll
        for (int kl4 = 0; kl4 < 32; kl4 += 4) {
            const float4 w4 = *(const float4*)&Wtv[(kl4 >> 2) * 512 + o * 4];
            #pragma unroll
            for (int r = 0; r < GEMM_ROWS; r++) {
                const float4 xv = *(const float4*)&xs[r * 32 + kl4];
                acc[r] = fmaf(w4.x, xv.x, acc[r]);
                acc[r] = fmaf(w4.y, xv.y, acc[r]);
                acc[r] = fmaf(w4.z, xv.z, acc[r]);
                acc[r] = fmaf(w4.w, xv.w, acc[r]);
            }
        }
    }

    #pragma unroll
    for (int r = 0; r < GEMM_ROWS; r++)
        z[(row0 + r) * DD + o] = acc[r];
}

// ---------------------------------------------------------------------------
// 5) aggregate: out[i] = ( sum_{j in row i bits} z[j] + z[i] ) / (popc+1)
//    One block per row, 128 threads (one per feature).  Scan the 256 bitmask
//    words (2 per thread), compact set-bit indices into a shared list, then
//    gather z rows (512B coalesced loads, z is L2-resident).
// ---------------------------------------------------------------------------
#define MAX_DEG 1024   // max row degree ~ Poisson(32); 1024 is >> any realization
__global__ void __launch_bounds__(128) agg_kernel(
    const float* __restrict__ z, float* __restrict__ out)
{
    __shared__ int list[MAX_DEG];
    __shared__ int cnt;

    const int i = blockIdx.x;
    const int t = threadIdx.x;

    if (t == 0) cnt = 0;
    __syncthreads();

    #pragma unroll
    for (int w = t; w < WORDS_PER_ROW; w += 128) {
        uint32_t word = g_bits[i * WORDS_PER_ROW + w];
        int pc = __popc(word);
        if (pc) {
            int base = atomicAdd(&cnt, pc);
            while (word) {
                int bpos = __ffs(word) - 1;
                word &= word - 1;
                list[base++] = (w << 5) + bpos;
            }
        }
    }
    __syncthreads();

    const int n = cnt;
    float acc = z[i * DD + t];              // self-loop contribution
    for (int idx = 0; idx < n; idx++) {
        int j = list[idx];
        acc += __ldg(&z[j * DD + t]);
    }
    out[i * DD + t] = acc * (1.0f / (float)(n + 1));
}

// ---------------------------------------------------------------------------
// launch
// ---------------------------------------------------------------------------
extern "C" void kernel_launch(void* const* d_in, const int* in_sizes, int n_in,
                              void* d_out, int out_size)
{
    const float* x = nullptr;
    const float* W = nullptr;
    const float* b = nullptr;
    const void*  edges = nullptr;

    for (int i = 0; i < n_in; i++) {
        switch (in_sizes[i]) {
            case NN * DD:   x = (const float*)d_in[i]; break;     // 1048576
            case 2 * EE:    edges = d_in[i];           break;     // 524288
            case DD * DD:   W = (const float*)d_in[i]; break;     // 16384
            case DD:        b = (const float*)d_in[i]; break;     // 128
            default: break;
        }
    }

    float* zbuf;
    cudaGetSymbolAddress((void**)&zbuf, g_z);

    clear_bits_kernel<<<(NN * WORDS_PER_ROW / 4) / 256, 256>>>();
    detect_kernel<<<1, 32>>>((const uint32_t*)edges);
    scatter_kernel<<<EE / 256, 256>>>(edges);
    gemm_kernel<<<NN / GEMM_ROWS, 128>>>(x, W, b, zbuf);
    agg_kernel<<<NN, 128>>>(zbuf, (float*)d_out);
}

// round 2
// speedup vs baseline: 1.2893x; 1.2893x over previous
#include <cuda_runtime.h>
#include <cuda_fp16.h>
#include <cstdint>

// Problem constants (fixed shapes)
#define NN    8192
#define EE    262144
#define DD    128
#define WORDS_PER_ROW (NN / 32)   // 256

// Device scratch (no allocations allowed)
__device__ uint32_t g_bits[NN * WORDS_PER_ROW];   // 8 MB binary adjacency
__device__ __half   g_zh[NN * DD];                // 2 MB  z = x @ W^T + b (fp16)
__device__ int      g_is64;

// ---------------------------------------------------------------------------
// 1) clear bitmask + detect int64/int32 edge encoding (block 0, warp 0)
// ---------------------------------------------------------------------------
__global__ void __launch_bounds__(256) clear_detect_kernel(const uint32_t* __restrict__ edges) {
    int i = blockIdx.x * 256 + threadIdx.x;   // 2048 blocks, uint4 each
    reinterpret_cast<uint4*>(g_bits)[i] = make_uint4(0u, 0u, 0u, 0u);
    if (blockIdx.x == 0 && threadIdx.x < 32) {
        // int64 values < 8192 -> every odd uint32 word is 0
        uint32_t v = 0;
        for (int k = threadIdx.x; k < 256; k += 32) v |= edges[2 * k + 1];
        #pragma unroll
        for (int o = 16; o; o >>= 1) v |= __shfl_xor_sync(0xFFFFFFFFu, v, o);
        if (threadIdx.x == 0) g_is64 = (v == 0u) ? 1 : 0;
    }
}

// ---------------------------------------------------------------------------
// 2) FUSED kernel:
//    blocks [0,256)        : z = x @ W^T + b  (fp32 math, fp16 store)
//    blocks [256, 256+1024): scatter edges into bitmask (set semantics)
//    Independent work; scatter overlaps with compute-bound gemm.
// ---------------------------------------------------------------------------
#define GEMM_BLOCKS   256
#define SCAT_BLOCKS   (EE / 256)          // 1024
#define WS_PITCH      132                 // floats; mult of 4, conflict-free reads
#define XS_PITCH      36

__global__ void __launch_bounds__(256) fused_gemm_scatter_kernel(
    const float* __restrict__ x, const float* __restrict__ W,
    const float* __restrict__ b, const void* __restrict__ edges)
{
    if (blockIdx.x >= GEMM_BLOCKS) {
        // ----- scatter -----
        int e = (blockIdx.x - GEMM_BLOCKS) * 256 + threadIdx.x;   // < EE exactly
        int s, d;
        if (g_is64) {
            const long long* p = (const long long*)edges;
            s = (int)p[e];
            d = (int)p[EE + e];
        } else {
            const int* p = (const int*)edges;
            s = p[e];
            d = p[EE + e];
        }
        atomicOr(&g_bits[s * WORDS_PER_ROW + (d >> 5)], 1u << (d & 31));
        return;
    }

    // ----- gemm: 32 rows x 128 cols per block, 4x4 per thread -----
    __shared__ float Ws[32 * WS_PITCH];   // [k][o] transposed W tile, 16.5 KB
    __shared__ float xs[32 * XS_PITCH];   // [row][k] x tile, 4.5 KB

    const int tid  = threadIdx.x;
    const int tc   = tid & 31;            // col group: cols 4*tc .. 4*tc+3
    const int tr   = tid >> 5;            // row group: rows 4*tr .. 4*tr+3 (== warp id)
    const int row0 = blockIdx.x * 32;

    float4 acc[4];
    const float4 b4 = reinterpret_cast<const float4*>(b)[tc];
    #pragma unroll
    for (int r = 0; r < 4; r++) acc[r] = b4;

    for (int kt = 0; kt < DD; kt += 32) {
        __syncthreads();
        // load + transpose W tile: W[o][kt..kt+31] -> Ws[k][o]
        #pragma unroll
        for (int p = 0; p < 4; p++) {
            int f  = tid + p * 256;       // float4 index, 0..1023
            int o  = f >> 3;
            int kq = f & 7;
            float4 v = reinterpret_cast<const float4*>(W + o * DD + kt)[kq];
            Ws[(4 * kq + 0) * WS_PITCH + o] = v.x;
            Ws[(4 * kq + 1) * WS_PITCH + o] = v.y;
            Ws[(4 * kq + 2) * WS_PITCH + o] = v.z;
            Ws[(4 * kq + 3) * WS_PITCH + o] = v.w;
        }
        // load x tile: 32 rows x 32 k
        {
            int row = tid >> 3;
            int kq  = tid & 7;
            float4 v = reinterpret_cast<const float4*>(x + (row0 + row) * DD + kt)[kq];
            *reinterpret_cast<float4*>(&xs[row * XS_PITCH + 4 * kq]) = v;
        }
        __syncthreads();

        #pragma unroll
        for (int kq = 0; kq < 8; kq++) {
            const float4 w0 = *(const float4*)&Ws[(4 * kq + 0) * WS_PITCH + 4 * tc];
            const float4 w1 = *(const float4*)&Ws[(4 * kq + 1) * WS_PITCH + 4 * tc];
            const float4 w2 = *(const float4*)&Ws[(4 * kq + 2) * WS_PITCH + 4 * tc];
            const float4 w3 = *(const float4*)&Ws[(4 * kq + 3) * WS_PITCH + 4 * tc];
            #pragma unroll
            for (int r = 0; r < 4; r++) {
                const float4 xv = *(const float4*)&xs[(4 * tr + r) * XS_PITCH + 4 * kq];
                acc[r].x = fmaf(xv.x, w0.x, acc[r].x);
                acc[r].y = fmaf(xv.x, w0.y, acc[r].y);
                acc[r].z = fmaf(xv.x, w0.z, acc[r].z);
                acc[r].w = fmaf(xv.x, w0.w, acc[r].w);
                acc[r].x = fmaf(xv.y, w1.x, acc[r].x);
                acc[r].y = fmaf(xv.y, w1.y, acc[r].y);
                acc[r].z = fmaf(xv.y, w1.z, acc[r].z);
                acc[r].w = fmaf(xv.y, w1.w, acc[r].w);
                acc[r].x = fmaf(xv.z, w2.x, acc[r].x);
                acc[r].y = fmaf(xv.z, w2.y, acc[r].y);
                acc[r].z = fmaf(xv.z, w2.z, acc[r].z);
                acc[r].w = fmaf(xv.z, w2.w, acc[r].w);
                acc[r].x = fmaf(xv.w, w3.x, acc[r].x);
                acc[r].y = fmaf(xv.w, w3.y, acc[r].y);
                acc[r].z = fmaf(xv.w, w3.z, acc[r].z);
                acc[r].w = fmaf(xv.w, w3.w, acc[r].w);
            }
        }
    }

    // store z as fp16 (half2 pairs)
    #pragma unroll
    for (int r = 0; r < 4; r++) {
        int row = row0 + 4 * tr + r;
        __half2* p = reinterpret_cast<__half2*>(g_zh + row * DD + 4 * tc);
        p[0] = __floats2half2_rn(acc[r].x, acc[r].y);
        p[1] = __floats2half2_rn(acc[r].z, acc[r].w);
    }
}

// ---------------------------------------------------------------------------
// 3) aggregate: out[i] = ( sum_{j in row i bits} z[j] + z[i] ) / (deg+1)
//    One block per row, 64 threads, each thread = 2 features (half2 gather).
// ---------------------------------------------------------------------------
#define MAX_DEG 1024
__global__ void __launch_bounds__(64) agg_kernel(float* __restrict__ out)
{
    __shared__ int list[MAX_DEG];
    __shared__ int cnt;

    const int i = blockIdx.x;
    const int t = threadIdx.x;            // 0..63
    const __half2* z2 = reinterpret_cast<const __half2*>(g_zh);

    if (t == 0) cnt = 0;
    __syncthreads();

    #pragma unroll
    for (int w = t; w < WORDS_PER_ROW; w += 64) {
        uint32_t word = g_bits[i * WORDS_PER_ROW + w];
        int pc = __popc(word);
        if (pc) {
            int base = atomicAdd(&cnt, pc);
            while (word) {
                int bpos = __ffs(word) - 1;
                word &= word - 1;
                list[base++] = (w << 5) + bpos;
            }
        }
    }
    __syncthreads();

    const int n = cnt;
    float2 f0 = __half22float2(z2[i * 64 + t]);   // self-loop
    float accx = f0.x, accy = f0.y;

    int idx = 0;
    for (; idx + 4 <= n; idx += 4) {              // MLP-4 batched gathers
        int j0 = list[idx + 0], j1 = list[idx + 1];
        int j2 = list[idx + 2], j3 = list[idx + 3];
        float2 v0 = __half22float2(z2[j0 * 64 + t]);
        float2 v1 = __half22float2(z2[j1 * 64 + t]);
        float2 v2 = __half22float2(z2[j2 * 64 + t]);
        float2 v3 = __half22float2(z2[j3 * 64 + t]);
        accx += (v0.x + v1.x) + (v2.x + v3.x);
        accy += (v0.y + v1.y) + (v2.y + v3.y);
    }
    for (; idx < n; idx++) {
        float2 v = __half22float2(z2[list[idx] * 64 + t]);
        accx += v.x;
        accy += v.y;
    }

    const float inv = 1.0f / (float)(n + 1);
    reinterpret_cast<float2*>(out)[i * 64 + t] = make_float2(accx * inv, accy * inv);
}

// ---------------------------------------------------------------------------
// launch
// ---------------------------------------------------------------------------
extern "C" void kernel_launch(void* const* d_in, const int* in_sizes, int n_in,
                              void* d_out, int out_size)
{
    const float* x = nullptr;
    const float* W = nullptr;
    const float* b = nullptr;
    const void*  edges = nullptr;

    for (int i = 0; i < n_in; i++) {
        switch (in_sizes[i]) {
            case NN * DD:   x = (const float*)d_in[i]; break;     // 1048576
            case 2 * EE:    edges = d_in[i];           break;     // 524288
            case DD * DD:   W = (const float*)d_in[i]; break;     // 16384
            case DD:        b = (const float*)d_in[i]; break;     // 128
            default: break;
        }
    }

    clear_detect_kernel<<<(NN * WORDS_PER_ROW / 4) / 256, 256>>>((const uint32_t*)edges);
    fused_gemm_scatter_kernel<<<GEMM_BLOCKS + SCAT_BLOCKS, 256>>>(x, W, b, edges);
    agg_kernel<<<NN, 64>>>((float*)d_out);
}

// round 3
// speedup vs baseline: 1.4031x; 1.0882x over previous
#include <cuda_runtime.h>
#include <cuda_fp16.h>
#include <cstdint>

// Problem constants (fixed shapes)
#define NN    8192
#define EE    262144
#define DD    128
#define WORDS_PER_ROW (NN / 32)   // 256

// Device scratch (no allocations allowed)
__device__ uint32_t g_bits[NN * WORDS_PER_ROW];   // 8 MB binary adjacency
__device__ __half   g_zh[NN * DD];                // 2 MB  z = x @ W^T + b (fp16)
__device__ int      g_is64;

// ---------------------------------------------------------------------------
// 1) FUSED kernel: clear bitmask + detect edge dtype + z = x @ W^T + b
//    128 blocks x 256 threads.  Each block:
//      - fire-and-forget clears its 64KB bitmask chunk (drains under compute)
//      - computes a 64-row x 128-col tile of z (8x4 per thread), stores fp16
//    Block 0 warp 0 additionally detects int64 vs int32 edge encoding.
// ---------------------------------------------------------------------------
#define GEMM_BLOCKS 128
#define KT          16          // K tile
#define WS_PITCH    132         // floats (mult of 4; 2-way store conflict only)
#define XS_PITCH    68

__global__ void __launch_bounds__(256) fused_clear_gemm_kernel(
    const float* __restrict__ x, const float* __restrict__ W,
    const float* __restrict__ b, const uint32_t* __restrict__ edges)
{
    __shared__ float Ws[KT * WS_PITCH];   // [k][o]   8.25 KB
    __shared__ float Xs[KT * XS_PITCH];   // [k][row] 4.25 KB

    const int tid = threadIdx.x;

    // ---- clear our bitmask chunk: 64KB = 4096 uint4, 16 per thread ----
    {
        uint4* bits4 = reinterpret_cast<uint4*>(g_bits) + blockIdx.x * 4096;
        const uint4 z4 = make_uint4(0u, 0u, 0u, 0u);
        #pragma unroll
        for (int i = 0; i < 16; i++) bits4[i * 256 + tid] = z4;
    }

    // ---- detect int64 vs int32 (block 0 warp 0): odd words all 0 => int64 ----
    if (blockIdx.x == 0 && tid < 32) {
        uint32_t v = 0;
        for (int k = tid; k < 256; k += 32) v |= edges[2 * k + 1];
        #pragma unroll
        for (int o = 16; o; o >>= 1) v |= __shfl_xor_sync(0xFFFFFFFFu, v, o);
        if (tid == 0) g_is64 = (v == 0u) ? 1 : 0;
    }

    // ---- gemm: rows row0..row0+63, cols 0..127 ----
    const int tc   = tid & 31;        // cols 4*tc .. 4*tc+3
    const int tr   = tid >> 5;        // rows 8*tr .. 8*tr+7 (warp id)
    const int row0 = blockIdx.x * 64;

    float4 acc[8];
    const float4 b4 = reinterpret_cast<const float4*>(b)[tc];
    #pragma unroll
    for (int r = 0; r < 8; r++) acc[r] = b4;

    for (int kt = 0; kt < DD; kt += KT) {
        __syncthreads();
        // W tile 128 o x 16 k -> Ws[k][o]   (512 float4 loads, 2/thread)
        #pragma unroll
        for (int p = 0; p < 2; p++) {
            int f  = tid + p * 256;       // 0..511
            int o  = f >> 2;
            int kq = f & 3;
            float4 v = reinterpret_cast<const float4*>(W + o * DD + kt)[kq];
            Ws[(4 * kq + 0) * WS_PITCH + o] = v.x;
            Ws[(4 * kq + 1) * WS_PITCH + o] = v.y;
            Ws[(4 * kq + 2) * WS_PITCH + o] = v.z;
            Ws[(4 * kq + 3) * WS_PITCH + o] = v.w;
        }
        // x tile 64 rows x 16 k -> Xs[k][row]  (256 float4 loads, 1/thread)
        {
            int row = tid >> 2;
            int kq  = tid & 3;
            float4 v = reinterpret_cast<const float4*>(x + (row0 + row) * DD + kt)[kq];
            Xs[(4 * kq + 0) * XS_PITCH + row] = v.x;
            Xs[(4 * kq + 1) * XS_PITCH + row] = v.y;
            Xs[(4 * kq + 2) * XS_PITCH + row] = v.z;
            Xs[(4 * kq + 3) * XS_PITCH + row] = v.w;
        }
        __syncthreads();

        #pragma unroll
        for (int k = 0; k < KT; k++) {
            const float4 w4 = *(const float4*)&Ws[k * WS_PITCH + 4 * tc];
            const float4 xa = *(const float4*)&Xs[k * XS_PITCH + 8 * tr];
            const float4 xb = *(const float4*)&Xs[k * XS_PITCH + 8 * tr + 4];
            #pragma unroll
            for (int r = 0; r < 4; r++) {
                const float xv = (&xa.x)[r];
                acc[r].x = fmaf(xv, w4.x, acc[r].x);
                acc[r].y = fmaf(xv, w4.y, acc[r].y);
                acc[r].z = fmaf(xv, w4.z, acc[r].z);
                acc[r].w = fmaf(xv, w4.w, acc[r].w);
            }
            #pragma unroll
            for (int r = 0; r < 4; r++) {
                const float xv = (&xb.x)[r];
                acc[4 + r].x = fmaf(xv, w4.x, acc[4 + r].x);
                acc[4 + r].y = fmaf(xv, w4.y, acc[4 + r].y);
                acc[4 + r].z = fmaf(xv, w4.z, acc[4 + r].z);
                acc[4 + r].w = fmaf(xv, w4.w, acc[4 + r].w);
            }
        }
    }

    // store z as fp16
    #pragma unroll
    for (int r = 0; r < 8; r++) {
        int row = row0 + 8 * tr + r;
        __half2* p = reinterpret_cast<__half2*>(g_zh + row * DD + 4 * tc);
        p[0] = __floats2half2_rn(acc[r].x, acc[r].y);
        p[1] = __floats2half2_rn(acc[r].z, acc[r].w);
    }
}

// ---------------------------------------------------------------------------
// 2) scatter edges into bitmask (set semantics), 2 edges per thread.
// ---------------------------------------------------------------------------
__global__ void __launch_bounds__(256) scatter_kernel(const void* __restrict__ edges)
{
    int base = (blockIdx.x * 256 + threadIdx.x) * 2;   // grid covers EE exactly
    if (g_is64) {
        const longlong2* ps = (const longlong2*)edges;             // src pairs
        const longlong2* pd = ps + EE / 2;                         // dst pairs
        longlong2 s2 = ps[base >> 1];
        longlong2 d2 = pd[base >> 1];
        int s0 = (int)s2.x, d0 = (int)d2.x;
        int s1 = (int)s2.y, d1 = (int)d2.y;
        atomicOr(&g_bits[s0 * WORDS_PER_ROW + (d0 >> 5)], 1u << (d0 & 31));
        atomicOr(&g_bits[s1 * WORDS_PER_ROW + (d1 >> 5)], 1u << (d1 & 31));
    } else {
        const int2* ps = (const int2*)edges;
        const int2* pd = ps + EE / 2;
        int2 s2 = ps[base >> 1];
        int2 d2 = pd[base >> 1];
        atomicOr(&g_bits[s2.x * WORDS_PER_ROW + (d2.x >> 5)], 1u << (d2.x & 31));
        atomicOr(&g_bits[s2.y * WORDS_PER_ROW + (d2.y >> 5)], 1u << (d2.y & 31));
    }
}

// ---------------------------------------------------------------------------
// 3) aggregate: out[i] = ( sum_{j in row i bits} z[j] + z[i] ) / (deg+1)
//    One block per row, 64 threads, each thread = 2 features (half2 gather).
// ---------------------------------------------------------------------------
#define MAX_DEG 1024
__global__ void __launch_bounds__(64) agg_kernel(float* __restrict__ out)
{
    __shared__ int list[MAX_DEG];
    __shared__ int cnt;

    const int i = blockIdx.x;
    const int t = threadIdx.x;            // 0..63
    const __half2* z2 = reinterpret_cast<const __half2*>(g_zh);

    if (t == 0) cnt = 0;
    __syncthreads();

    #pragma unroll
    for (int w = t; w < WORDS_PER_ROW; w += 64) {
        uint32_t word = g_bits[i * WORDS_PER_ROW + w];
        int pc = __popc(word);
        if (pc) {
            int base = atomicAdd(&cnt, pc);
            while (word) {
                int bpos = __ffs(word) - 1;
                word &= word - 1;
                list[base++] = (w << 5) + bpos;
            }
        }
    }
    __syncthreads();

    const int n = cnt;
    float2 f0 = __half22float2(z2[i * 64 + t]);   // self-loop
    float accx = f0.x, accy = f0.y;

    int idx = 0;
    for (; idx + 4 <= n; idx += 4) {              // MLP-4 batched gathers
        int j0 = list[idx + 0], j1 = list[idx + 1];
        int j2 = list[idx + 2], j3 = list[idx + 3];
        float2 v0 = __half22float2(z2[j0 * 64 + t]);
        float2 v1 = __half22float2(z2[j1 * 64 + t]);
        float2 v2 = __half22float2(z2[j2 * 64 + t]);
        float2 v3 = __half22float2(z2[j3 * 64 + t]);
        accx += (v0.x + v1.x) + (v2.x + v3.x);
        accy += (v0.y + v1.y) + (v2.y + v3.y);
    }
    for (; idx < n; idx++) {
        float2 v = __half22float2(z2[list[idx] * 64 + t]);
        accx += v.x;
        accy += v.y;
    }

    const float inv = 1.0f / (float)(n + 1);
    reinterpret_cast<float2*>(out)[i * 64 + t] = make_float2(accx * inv, accy * inv);
}

// ---------------------------------------------------------------------------
// launch
// ---------------------------------------------------------------------------
extern "C" void kernel_launch(void* const* d_in, const int* in_sizes, int n_in,
                              void* d_out, int out_size)
{
    const float* x = nullptr;
    const float* W = nullptr;
    const float* b = nullptr;
    const void*  edges = nullptr;

    for (int i = 0; i < n_in; i++) {
        switch (in_sizes[i]) {
            case NN * DD:   x = (const float*)d_in[i]; break;     // 1048576
            case 2 * EE:    edges = d_in[i];           break;     // 524288
            case DD * DD:   W = (const float*)d_in[i]; break;     // 16384
            case DD:        b = (const float*)d_in[i]; break;     // 128
            default: break;
        }
    }

    fused_clear_gemm_kernel<<<GEMM_BLOCKS, 256>>>(x, W, b, (const uint32_t*)edges);
    scatter_kernel<<<EE / 512, 256>>>(edges);
    agg_kernel<<<NN, 64>>>((float*)d_out);
}